// round 1
// baseline (speedup 1.0000x reference)
#include <cuda_runtime.h>
#include <cuda_bf16.h>
#include <cstdint>
#include <cstdio>

#define N_ENT 50000
#define N_USR 10000
#define NND   60000
#define NEDGE 1920000
#define NREL  16
#define BATCH 4096

// ---------------- scratch (device globals; no allocation allowed) ----------------
__device__ float g_encoded[NND * 32];
__device__ float g_x1[NND * 32];
__device__ float g_x2[NND * 16];
__device__ float g_agg[NND * 32];
__device__ int   g_cnt[NND];
__device__ float g_gd[NND * 16];
__device__ float g_gs[NND * 16];
__device__ float g_wsum1[NREL * 64];
__device__ float g_wsum2[NREL * 64];
__device__ float g_loss;

// ---------------- zero kernels (buffers persist across graph replays!) -----------
__global__ void __launch_bounds__(256) zero_all_kernel() {
    int i  = blockIdx.x * blockDim.x + threadIdx.x;
    int st = gridDim.x * blockDim.x;
    for (int k = i; k < NND * 32; k += st) g_agg[k] = 0.f;
    for (int k = i; k < NND; k += st) g_cnt[k] = 0;
    if (i == 0) g_loss = 0.f;
}

__global__ void __launch_bounds__(256) zero_agg_kernel() {
    int i  = blockIdx.x * blockDim.x + threadIdx.x;
    int st = gridDim.x * blockDim.x;
    for (int k = i; k < NND * 32; k += st) g_agg[k] = 0.f;
}

// ---------------- w_sum = W_r.sum(-1) for both layers ----------------------------
__global__ void __launch_bounds__(256) wsum_kernel(const float* __restrict__ Wr1,
                                                   const float* __restrict__ Wr2) {
    int i = blockIdx.x * blockDim.x + threadIdx.x;
    if (i >= 2 * NREL * 64) return;
    const float* W = (i < NREL * 64) ? Wr1 : Wr2;
    float* o       = (i < NREL * 64) ? g_wsum1 : g_wsum2;
    int j          = i & (NREL * 64 - 1);
    const float* p = W + j * 32;
    float s = 0.f;
#pragma unroll
    for (int t = 0; t < 32; t++) s += p[t];
    o[j] = s;
}

// ---------------- degree count (once; same graph both layers) --------------------
__global__ void __launch_bounds__(256) count_kernel(const int* __restrict__ edst) {
    int e = blockIdx.x * blockDim.x + threadIdx.x;
    if (e < NEDGE) atomicAdd(&g_cnt[edst[e]], 1);
}

// ---------------- autoencoder: encode ([64]->relu[128]->[32]) --------------------
__global__ void __launch_bounds__(256) encode_kernel(
    const float* __restrict__ ent, const float* __restrict__ usr,
    const float* __restrict__ W0, const float* __restrict__ b0,
    const float* __restrict__ W1, const float* __restrict__ b1) {
    __shared__ float sW0[64 * 128];   // 32 KB
    __shared__ float sW1[128 * 32];   // 16 KB (total 48 KB static)
    for (int i = threadIdx.x; i < 64 * 128; i += 256) sW0[i] = W0[i];
    for (int i = threadIdx.x; i < 128 * 32; i += 256) sW1[i] = W1[i];
    __syncthreads();

    const int lane  = threadIdx.x & 31;
    const int wid   = (blockIdx.x * 256 + threadIdx.x) >> 5;
    const int nwarp = (gridDim.x * 256) >> 5;

    float bb0[4];
#pragma unroll
    for (int p = 0; p < 4; p++) bb0[p] = b0[lane + 32 * p];
    const float bb1 = b1[lane];

    for (int n = wid; n < NND; n += nwarp) {
        const float* e = (n < N_ENT) ? (ent + (size_t)n * 64)
                                     : (usr + (size_t)(n - N_ENT) * 64);
        float e0 = e[lane], e1 = e[lane + 32];
        float h0 = bb0[0], h1 = bb0[1], h2 = bb0[2], h3 = bb0[3];
#pragma unroll
        for (int k = 0; k < 64; k++) {
            float b = __shfl_sync(0xffffffffu, (k < 32) ? e0 : e1, k & 31);
            const float* w = sW0 + k * 128 + lane;
            h0 = fmaf(b, w[0],  h0);
            h1 = fmaf(b, w[32], h1);
            h2 = fmaf(b, w[64], h2);
            h3 = fmaf(b, w[96], h3);
        }
        h0 = fmaxf(h0, 0.f); h1 = fmaxf(h1, 0.f);
        h2 = fmaxf(h2, 0.f); h3 = fmaxf(h3, 0.f);
        float acc = bb1;
#pragma unroll
        for (int k = 0; k < 128; k++) {
            float hv = (k < 32) ? h0 : (k < 64) ? h1 : (k < 96) ? h2 : h3;
            float b  = __shfl_sync(0xffffffffu, hv, k & 31);
            acc = fmaf(b, sW1[k * 32 + lane], acc);
        }
        g_encoded[n * 32 + lane] = acc;
    }
}

// ---------------- autoencoder: decode ([32]->relu[128]->[64]) + sq-err loss ------
__global__ void __launch_bounds__(256) decode_kernel(
    const float* __restrict__ ent, const float* __restrict__ usr,
    const float* __restrict__ W0, const float* __restrict__ b0,
    const float* __restrict__ W1, const float* __restrict__ b1) {
    __shared__ float sW0[32 * 128];   // 16 KB
    __shared__ float sW1[128 * 64];   // 32 KB (48 KB static total)
    for (int i = threadIdx.x; i < 32 * 128; i += 256) sW0[i] = W0[i];
    for (int i = threadIdx.x; i < 128 * 64; i += 256) sW1[i] = W1[i];
    __syncthreads();

    const int lane  = threadIdx.x & 31;
    const int wid   = (blockIdx.x * 256 + threadIdx.x) >> 5;
    const int nwarp = (gridDim.x * 256) >> 5;

    float bb0[4];
#pragma unroll
    for (int p = 0; p < 4; p++) bb0[p] = b0[lane + 32 * p];
    const float bb1a = b1[lane], bb1b = b1[lane + 32];

    float lsum = 0.f;
    for (int n = wid; n < NND; n += nwarp) {
        float ev = g_encoded[n * 32 + lane];
        float h0 = bb0[0], h1 = bb0[1], h2 = bb0[2], h3 = bb0[3];
#pragma unroll
        for (int k = 0; k < 32; k++) {
            float b = __shfl_sync(0xffffffffu, ev, k);
            const float* w = sW0 + k * 128 + lane;
            h0 = fmaf(b, w[0],  h0);
            h1 = fmaf(b, w[32], h1);
            h2 = fmaf(b, w[64], h2);
            h3 = fmaf(b, w[96], h3);
        }
        h0 = fmaxf(h0, 0.f); h1 = fmaxf(h1, 0.f);
        h2 = fmaxf(h2, 0.f); h3 = fmaxf(h3, 0.f);
        float d0 = bb1a, d1 = bb1b;
#pragma unroll
        for (int k = 0; k < 128; k++) {
            float hv = (k < 32) ? h0 : (k < 64) ? h1 : (k < 96) ? h2 : h3;
            float b  = __shfl_sync(0xffffffffu, hv, k & 31);
            d0 = fmaf(b, sW1[k * 64 + lane],      d0);
            d1 = fmaf(b, sW1[k * 64 + lane + 32], d1);
        }
        const float* e = (n < N_ENT) ? (ent + (size_t)n * 64)
                                     : (usr + (size_t)(n - N_ENT) * 64);
        float q0 = d0 - e[lane], q1 = d1 - e[lane + 32];
        lsum += q0 * q0 + q1 * q1;
    }
#pragma unroll
    for (int o = 16; o; o >>= 1) lsum += __shfl_xor_sync(0xffffffffu, lsum, o);
    if (lane == 0) atomicAdd(&g_loss, lsum);
}

// ---------------- per-node per-relation gate dots: gd/gs [N,16] ------------------
__global__ void __launch_bounds__(256) gate_kernel(int layer) {
    const float* x  = (layer == 1) ? g_encoded : g_x1;
    const float* ws = (layer == 1) ? g_wsum1 : g_wsum2;
    __shared__ float sWd[32 * 16];   // [k][r] : wsum[r][k],    k<32
    __shared__ float sWs[32 * 16];   // [k][r] : wsum[r][32+k]
    for (int i = threadIdx.x; i < NREL * 64; i += 256) {
        int r = i >> 6, k = i & 63;
        float v = ws[i];
        if (k < 32) sWd[k * 16 + r] = v;
        else        sWs[(k - 32) * 16 + r] = v;
    }
    __syncthreads();

    int wid = (blockIdx.x * 256 + threadIdx.x) >> 5;
    if (wid >= NND) return;
    int lane = threadIdx.x & 31;
    int r    = lane & 15;
    const float* base = (lane >= 16) ? sWs : sWd;
    float xv  = x[wid * 32 + lane];
    float acc = 0.f;
#pragma unroll
    for (int k = 0; k < 32; k++) {
        float b = __shfl_sync(0xffffffffu, xv, k);
        acc = fmaf(b, base[k * 16 + r], acc);
    }
    if (lane < 16) g_gd[wid * 16 + r] = acc;
    else           g_gs[wid * 16 + r] = acc;
}

// ---------------- edge scatter: agg[dst] += sigmoid(gate) * x[src] ---------------
// 8 lanes per edge, 4 dims per lane, vectorized fp32 reduction to gmem.
__global__ void __launch_bounds__(256) edge_kernel(int layer,
                                                   const int* __restrict__ esrc,
                                                   const int* __restrict__ edst,
                                                   const int* __restrict__ erel) {
    const float* x = (layer == 1) ? g_encoded : g_x1;
    long long t = (long long)blockIdx.x * 256 + threadIdx.x;
    int e = (int)(t >> 3);
    if (e >= NEDGE) return;
    int sub = (int)(t & 7);
    int s = esrc[e], d = edst[e], r = erel[e];
    float gl   = g_gd[d * 16 + r] + g_gs[s * 16 + r];
    float gate = 1.f / (1.f + __expf(-gl));
    const float4 h = *reinterpret_cast<const float4*>(x + (size_t)s * 32 + sub * 4);
    float* a = g_agg + (size_t)d * 32 + sub * 4;
    asm volatile("red.global.add.v4.f32 [%0], {%1, %2, %3, %4};"
                 :: "l"(a), "f"(h.x * gate), "f"(h.y * gate),
                    "f"(h.z * gate), "f"(h.w * gate)
                 : "memory");
}

// ---------------- combine: leaky_relu(concat(x, mean-agg) @ W + b) ---------------
template <int LAYER>
__global__ void __launch_bounds__(256) combine_kernel(const float* __restrict__ linW,
                                                      const float* __restrict__ linb) {
    constexpr int OUT = (LAYER == 1) ? 32 : 16;
    const float* x = (LAYER == 1) ? g_encoded : g_x1;
    float* xo      = (LAYER == 1) ? g_x1 : g_x2;
    __shared__ float sW[64 * OUT];
    for (int i = threadIdx.x; i < 64 * OUT; i += 256) sW[i] = linW[i];
    __syncthreads();

    int wid = (blockIdx.x * 256 + threadIdx.x) >> 5;
    if (wid >= NND) return;
    int lane = threadIdx.x & 31;
    int j    = lane & (OUT - 1);
    float xv = x[wid * 32 + lane];
    int   c  = g_cnt[wid];
    float av = (c > 0) ? g_agg[wid * 32 + lane] / (float)c : 0.f;
    float acc = linb[j];
#pragma unroll
    for (int k = 0; k < 64; k++) {
        float src = (k < 32) ? xv : av;
        float b   = __shfl_sync(0xffffffffu, src, k & 31);
        acc = fmaf(b, sW[k * OUT + j], acc);
    }
    acc = (acc > 0.f) ? acc : 0.01f * acc;
    if (lane < OUT) xo[wid * OUT + lane] = acc;
}

// ---------------- scoring: dot(final[user_node], final[item]) --------------------
__global__ void __launch_bounds__(256) score_kernel(const int* __restrict__ users,
                                                    const int* __restrict__ items,
                                                    float* __restrict__ out) {
    int wid = (blockIdx.x * 256 + threadIdx.x) >> 5;
    if (wid >= BATCH) return;
    int lane = threadIdx.x & 31;
    int un = N_ENT + users[wid];
    int it = items[wid];
    float s = g_x1[(size_t)un * 32 + lane] * g_x1[(size_t)it * 32 + lane];
    if (lane < 16) s += g_x2[(size_t)un * 16 + lane] * g_x2[(size_t)it * 16 + lane];
#pragma unroll
    for (int o = 16; o; o >>= 1) s += __shfl_xor_sync(0xffffffffu, s, o);
    if (lane == 0) out[wid] = s;
}

__global__ void finalize_kernel(float* out, int out_size) {
    if (threadIdx.x == 0 && out_size > BATCH)
        out[BATCH] = g_loss * (1.0f / (float)(NND * 64));
}

// ---------------- host launcher --------------------------------------------------
extern "C" void kernel_launch(void* const* d_in, const int* in_sizes, int n_in,
                              void* d_out, int out_size) {
    // Default: setup_inputs dict order.
    int iu = 0, ii = 1, ies = 2, ied = 3, ier = 4, ient = 5, iusr = 6;
    int ie0 = 7, ib0 = 8, ie1 = 9, ib1 = 10, id0 = 11, idb0 = 12, id1 = 13, idb1 = 14;
    int iWr1 = 15, ilW1 = 16, ilb1 = 17, iWr2 = 18, ilW2 = 19, ilb2 = 20;
    bool dict_order = (n_in >= 21 && in_sizes[0] == BATCH && in_sizes[2] == NEDGE &&
                       in_sizes[5] == N_ENT * 64);
    if (!dict_order) {
        // reference-signature order fallback
        ient = 0; iusr = 1; ie0 = 2; ib0 = 3; ie1 = 4; ib1 = 5;
        id0 = 6; idb0 = 7; id1 = 8; idb1 = 9;
        iWr1 = 10; ilW1 = 11; ilb1 = 12; iWr2 = 13; ilW2 = 14; ilb2 = 15;
        iu = 16; ii = 17; ies = 18; ied = 19; ier = 20;
    }
    const int* users = (const int*)d_in[iu];
    const int* items = (const int*)d_in[ii];
    const int* esrc  = (const int*)d_in[ies];
    const int* edst  = (const int*)d_in[ied];
    const int* erel  = (const int*)d_in[ier];
    const float* ent = (const float*)d_in[ient];
    const float* usr = (const float*)d_in[iusr];
    float* out = (float*)d_out;

    zero_all_kernel<<<1920, 256>>>();
    wsum_kernel<<<8, 256>>>((const float*)d_in[iWr1], (const float*)d_in[iWr2]);
    count_kernel<<<(NEDGE + 255) / 256, 256>>>(edst);
    encode_kernel<<<592, 256>>>(ent, usr,
                                (const float*)d_in[ie0], (const float*)d_in[ib0],
                                (const float*)d_in[ie1], (const float*)d_in[ib1]);
    decode_kernel<<<592, 256>>>(ent, usr,
                                (const float*)d_in[id0], (const float*)d_in[idb0],
                                (const float*)d_in[id1], (const float*)d_in[idb1]);
    // layer 1
    gate_kernel<<<(NND + 7) / 8, 256>>>(1);
    edge_kernel<<<NEDGE * 8 / 256, 256>>>(1, esrc, edst, erel);
    combine_kernel<1><<<(NND + 7) / 8, 256>>>((const float*)d_in[ilW1],
                                              (const float*)d_in[ilb1]);
    // layer 2
    zero_agg_kernel<<<1920, 256>>>();
    gate_kernel<<<(NND + 7) / 8, 256>>>(2);
    edge_kernel<<<NEDGE * 8 / 256, 256>>>(2, esrc, edst, erel);
    combine_kernel<2><<<(NND + 7) / 8, 256>>>((const float*)d_in[ilW2],
                                              (const float*)d_in[ilb2]);
    // outputs
    score_kernel<<<(BATCH * 32 + 255) / 256, 256>>>(users, items, out);
    finalize_kernel<<<1, 32>>>(out, out_size);
}

// round 2
// speedup vs baseline: 1.3969x; 1.3969x over previous
#include <cuda_runtime.h>
#include <cuda_bf16.h>
#include <cstdint>
#include <cstdio>

#define N_ENT 50000
#define N_USR 10000
#define NND   60000
#define NEDGE 1920000
#define NREL  16
#define BATCH 4096

typedef unsigned long long ull;

// packed f32x2 FMA: d.lo += a.lo*b.lo ; d.hi += a.hi*b.hi  (one issue slot, 2 FMAs)
#define FFMA2(d, a, b) asm("fma.rn.f32x2 %0, %1, %2, %0;" : "+l"(d) : "l"(a), "l"(b))

__device__ __forceinline__ float f2lo(ull v) { return __uint_as_float((unsigned)v); }
__device__ __forceinline__ float f2hi(ull v) { return __uint_as_float((unsigned)(v >> 32)); }
__device__ __forceinline__ float f2sum(ull v) { return f2lo(v) + f2hi(v); }

// ---------------- scratch (device globals; no allocation allowed) ----------------
__device__ float g_encoded[NND * 32];
__device__ float g_x1[NND * 32];
__device__ float g_x2[NND * 16];
__device__ float g_agg[NND * 32];
__device__ int   g_cnt[NND];
__device__ float g_gd[NND * 16];
__device__ float g_gs[NND * 16];
__device__ float g_wsum1[NREL * 64];
__device__ float g_wsum2[NREL * 64];
__device__ float g_loss;

extern __shared__ unsigned char dynsmem[];

// ---------------- zero kernels (buffers persist across graph replays!) -----------
__global__ void __launch_bounds__(256) zero_all_kernel() {
    int i  = blockIdx.x * blockDim.x + threadIdx.x;
    int st = gridDim.x * blockDim.x;
    for (int k = i; k < NND * 32; k += st) g_agg[k] = 0.f;
    for (int k = i; k < NND; k += st) g_cnt[k] = 0;
    if (i == 0) g_loss = 0.f;
}

__global__ void __launch_bounds__(256) zero_agg_kernel() {
    int i  = blockIdx.x * blockDim.x + threadIdx.x;
    int st = gridDim.x * blockDim.x;
    for (int k = i; k < NND * 32; k += st) g_agg[k] = 0.f;
}

// ---------------- w_sum = W_r.sum(-1) for both layers ----------------------------
__global__ void __launch_bounds__(256) wsum_kernel(const float* __restrict__ Wr1,
                                                   const float* __restrict__ Wr2) {
    int i = blockIdx.x * blockDim.x + threadIdx.x;
    if (i >= 2 * NREL * 64) return;
    const float* W = (i < NREL * 64) ? Wr1 : Wr2;
    float* o       = (i < NREL * 64) ? g_wsum1 : g_wsum2;
    int j          = i & (NREL * 64 - 1);
    const float* p = W + j * 32;
    float s = 0.f;
#pragma unroll
    for (int t = 0; t < 32; t++) s += p[t];
    o[j] = s;
}

// ---------------- degree count (once; same graph both layers) --------------------
__global__ void __launch_bounds__(256) count_kernel(const int* __restrict__ edst) {
    int e = blockIdx.x * blockDim.x + threadIdx.x;
    if (e < NEDGE) atomicAdd(&g_cnt[edst[e]], 1);
}

// ---------------- autoencoder: encode ([64]->relu[128]->[32]) --------------------
// NB=4 nodes per warp pass; FFMA2 with k-pair packing; smem-staged broadcasts.
__global__ void __launch_bounds__(256, 3) encode_kernel(
    const float* __restrict__ ent, const float* __restrict__ usr,
    const float* __restrict__ W0, const float* __restrict__ b0,
    const float* __restrict__ W1, const float* __restrict__ b1) {
    float2* sW0 = (float2*)dynsmem;               // 32 k-pairs x 128 cols  (32 KB)
    float2* sW1 = sW0 + 32 * 128;                 // 64 k-pairs x 32 cols   (16 KB)
    float*  stg = (float*)(sW1 + 64 * 32);        // 8 warps x 512 floats   (16 KB)

    for (int i = threadIdx.x; i < 32 * 128; i += 256) {
        int k2 = i >> 7, j = i & 127;
        sW0[i] = make_float2(W0[(2 * k2) * 128 + j], W0[(2 * k2 + 1) * 128 + j]);
    }
    for (int i = threadIdx.x; i < 64 * 32; i += 256) {
        int k2 = i >> 5, j = i & 31;
        sW1[i] = make_float2(W1[(2 * k2) * 32 + j], W1[(2 * k2 + 1) * 32 + j]);
    }
    __syncthreads();

    const ull* sW0u = (const ull*)sW0;
    const ull* sW1u = (const ull*)sW1;
    const int lane  = threadIdx.x & 31;
    float* mystg    = stg + (threadIdx.x >> 5) * 512;
    ull*   mystgU   = (ull*)mystg;

    const int wid   = (blockIdx.x * 256 + threadIdx.x) >> 5;
    const int nwarp = (gridDim.x * 256) >> 5;

    float bb0[4];
#pragma unroll
    for (int p = 0; p < 4; p++) bb0[p] = b0[lane + 32 * p];
    const float bb1 = b1[lane];

    for (int g = wid; g < NND / 4; g += nwarp) {
        // stage 4 nodes' inputs (64 floats each, natural k-pair order)
#pragma unroll
        for (int m = 0; m < 4; m++) {
            int n = g * 4 + m;
            const float* e = (n < N_ENT) ? (ent + (size_t)n * 64)
                                         : (usr + (size_t)(n - N_ENT) * 64);
            ((float2*)mystg)[m * 32 + lane] = ((const float2*)e)[lane];
        }
        __syncwarp();

        // loop1: [64] -> [128], cols j = lane + 32p
        ull acc[4][4];
#pragma unroll
        for (int m = 0; m < 4; m++)
#pragma unroll
            for (int p = 0; p < 4; p++) acc[m][p] = 0ull;
#pragma unroll 8
        for (int k2 = 0; k2 < 32; k2++) {
            ull w0 = sW0u[k2 * 128 + lane];
            ull w1 = sW0u[k2 * 128 + lane + 32];
            ull w2 = sW0u[k2 * 128 + lane + 64];
            ull w3 = sW0u[k2 * 128 + lane + 96];
#pragma unroll
            for (int m = 0; m < 4; m++) {
                ull b = mystgU[m * 32 + k2];   // broadcast (x[2k2], x[2k2+1])
                FFMA2(acc[m][0], b, w0);
                FFMA2(acc[m][1], b, w1);
                FFMA2(acc[m][2], b, w2);
                FFMA2(acc[m][3], b, w3);
            }
        }
        __syncwarp();

        // relu(h + bias) -> stage (4 nodes x 128)
#pragma unroll
        for (int m = 0; m < 4; m++)
#pragma unroll
            for (int p = 0; p < 4; p++)
                mystg[m * 128 + lane + 32 * p] = fmaxf(f2sum(acc[m][p]) + bb0[p], 0.f);
        __syncwarp();

        // loop2: [128] -> [32], col j = lane
        ull a2[4] = {0ull, 0ull, 0ull, 0ull};
#pragma unroll 8
        for (int k2 = 0; k2 < 64; k2++) {
            ull w = sW1u[k2 * 32 + lane];
#pragma unroll
            for (int m = 0; m < 4; m++) {
                ull b = mystgU[m * 64 + k2];
                FFMA2(a2[m], b, w);
            }
        }
#pragma unroll
        for (int m = 0; m < 4; m++)
            g_encoded[(size_t)(g * 4 + m) * 32 + lane] = f2sum(a2[m]) + bb1;
        __syncwarp();
    }
}

// ---------------- autoencoder: decode ([32]->relu[128]->[64]) + sq-err loss ------
__global__ void __launch_bounds__(256, 3) decode_kernel(
    const float* __restrict__ ent, const float* __restrict__ usr,
    const float* __restrict__ W0, const float* __restrict__ b0,
    const float* __restrict__ W1, const float* __restrict__ b1) {
    float2* sW0 = (float2*)dynsmem;               // 16 k-pairs x 128 cols (16 KB)
    float2* sW1 = sW0 + 16 * 128;                 // 64 k-pairs x 64 cols  (32 KB)
    float*  stg = (float*)(sW1 + 64 * 64);        // 8 warps x 512 floats  (16 KB)

    for (int i = threadIdx.x; i < 16 * 128; i += 256) {
        int k2 = i >> 7, j = i & 127;
        sW0[i] = make_float2(W0[(2 * k2) * 128 + j], W0[(2 * k2 + 1) * 128 + j]);
    }
    for (int i = threadIdx.x; i < 64 * 64; i += 256) {
        int k2 = i >> 6, j = i & 63;
        sW1[i] = make_float2(W1[(2 * k2) * 64 + j], W1[(2 * k2 + 1) * 64 + j]);
    }
    __syncthreads();

    const ull* sW0u = (const ull*)sW0;
    const ull* sW1u = (const ull*)sW1;
    const int lane  = threadIdx.x & 31;
    float* mystg    = stg + (threadIdx.x >> 5) * 512;
    ull*   mystgU   = (ull*)mystg;

    const int wid   = (blockIdx.x * 256 + threadIdx.x) >> 5;
    const int nwarp = (gridDim.x * 256) >> 5;

    float bb0[4];
#pragma unroll
    for (int p = 0; p < 4; p++) bb0[p] = b0[lane + 32 * p];
    const float bb1a = b1[lane], bb1b = b1[lane + 32];

    float lsum = 0.f;
    for (int g = wid; g < NND / 4; g += nwarp) {
        // stage 4 nodes' encoded vectors (32 floats each)
#pragma unroll
        for (int m = 0; m < 4; m++)
            mystg[m * 32 + lane] = g_encoded[(size_t)(g * 4 + m) * 32 + lane];
        __syncwarp();

        // loop1: [32] -> [128]
        ull acc[4][4];
#pragma unroll
        for (int m = 0; m < 4; m++)
#pragma unroll
            for (int p = 0; p < 4; p++) acc[m][p] = 0ull;
#pragma unroll
        for (int k2 = 0; k2 < 16; k2++) {
            ull w0 = sW0u[k2 * 128 + lane];
            ull w1 = sW0u[k2 * 128 + lane + 32];
            ull w2 = sW0u[k2 * 128 + lane + 64];
            ull w3 = sW0u[k2 * 128 + lane + 96];
#pragma unroll
            for (int m = 0; m < 4; m++) {
                ull b = mystgU[m * 16 + k2];
                FFMA2(acc[m][0], b, w0);
                FFMA2(acc[m][1], b, w1);
                FFMA2(acc[m][2], b, w2);
                FFMA2(acc[m][3], b, w3);
            }
        }
        __syncwarp();
#pragma unroll
        for (int m = 0; m < 4; m++)
#pragma unroll
            for (int p = 0; p < 4; p++)
                mystg[m * 128 + lane + 32 * p] = fmaxf(f2sum(acc[m][p]) + bb0[p], 0.f);
        __syncwarp();

        // loop2: [128] -> [64], cols j = lane, lane+32
        ull a0[4] = {0ull, 0ull, 0ull, 0ull};
        ull a1[4] = {0ull, 0ull, 0ull, 0ull};
#pragma unroll 8
        for (int k2 = 0; k2 < 64; k2++) {
            ull w0 = sW1u[k2 * 64 + lane];
            ull w1 = sW1u[k2 * 64 + lane + 32];
#pragma unroll
            for (int m = 0; m < 4; m++) {
                ull b = mystgU[m * 64 + k2];
                FFMA2(a0[m], b, w0);
                FFMA2(a1[m], b, w1);
            }
        }
#pragma unroll
        for (int m = 0; m < 4; m++) {
            int n = g * 4 + m;
            const float* e = (n < N_ENT) ? (ent + (size_t)n * 64)
                                         : (usr + (size_t)(n - N_ENT) * 64);
            float q0 = (f2sum(a0[m]) + bb1a) - e[lane];
            float q1 = (f2sum(a1[m]) + bb1b) - e[lane + 32];
            lsum += q0 * q0 + q1 * q1;
        }
        __syncwarp();
    }
#pragma unroll
    for (int o = 16; o; o >>= 1) lsum += __shfl_xor_sync(0xffffffffu, lsum, o);
    if (lane == 0) atomicAdd(&g_loss, lsum);
}

// ---------------- per-node per-relation gate dots: gd/gs [N,16] ------------------
__global__ void __launch_bounds__(256) gate_kernel(int layer) {
    const float* x  = (layer == 1) ? g_encoded : g_x1;
    const float* ws = (layer == 1) ? g_wsum1 : g_wsum2;
    __shared__ float sWd[32 * 16];
    __shared__ float sWs[32 * 16];
    for (int i = threadIdx.x; i < NREL * 64; i += 256) {
        int r = i >> 6, k = i & 63;
        float v = ws[i];
        if (k < 32) sWd[k * 16 + r] = v;
        else        sWs[(k - 32) * 16 + r] = v;
    }
    __syncthreads();

    int wid = (blockIdx.x * 256 + threadIdx.x) >> 5;
    if (wid >= NND) return;
    int lane = threadIdx.x & 31;
    int r    = lane & 15;
    const float* base = (lane >= 16) ? sWs : sWd;
    float xv  = x[wid * 32 + lane];
    float acc = 0.f;
#pragma unroll
    for (int k = 0; k < 32; k++) {
        float b = __shfl_sync(0xffffffffu, xv, k);
        acc = fmaf(b, base[k * 16 + r], acc);
    }
    if (lane < 16) g_gd[wid * 16 + r] = acc;
    else           g_gs[wid * 16 + r] = acc;
}

// ---------------- edge scatter: agg[dst] += sigmoid(gate) * x[src] ---------------
__global__ void __launch_bounds__(256) edge_kernel(int layer,
                                                   const int* __restrict__ esrc,
                                                   const int* __restrict__ edst,
                                                   const int* __restrict__ erel) {
    const float* x = (layer == 1) ? g_encoded : g_x1;
    long long t = (long long)blockIdx.x * 256 + threadIdx.x;
    int e = (int)(t >> 3);
    if (e >= NEDGE) return;
    int sub = (int)(t & 7);
    int s = esrc[e], d = edst[e], r = erel[e];
    float gl   = g_gd[d * 16 + r] + g_gs[s * 16 + r];
    float gate = 1.f / (1.f + __expf(-gl));
    const float4 h = *reinterpret_cast<const float4*>(x + (size_t)s * 32 + sub * 4);
    float* a = g_agg + (size_t)d * 32 + sub * 4;
    asm volatile("red.global.add.v4.f32 [%0], {%1, %2, %3, %4};"
                 :: "l"(a), "f"(h.x * gate), "f"(h.y * gate),
                    "f"(h.z * gate), "f"(h.w * gate)
                 : "memory");
}

// ---------------- combine: leaky_relu(concat(x, mean-agg) @ W + b) ---------------
template <int LAYER>
__global__ void __launch_bounds__(256) combine_kernel(const float* __restrict__ linW,
                                                      const float* __restrict__ linb) {
    constexpr int OUT = (LAYER == 1) ? 32 : 16;
    const float* x = (LAYER == 1) ? g_encoded : g_x1;
    float* xo      = (LAYER == 1) ? g_x1 : g_x2;
    __shared__ float sW[64 * OUT];
    for (int i = threadIdx.x; i < 64 * OUT; i += 256) sW[i] = linW[i];
    __syncthreads();

    int wid = (blockIdx.x * 256 + threadIdx.x) >> 5;
    if (wid >= NND) return;
    int lane = threadIdx.x & 31;
    int j    = lane & (OUT - 1);
    float xv = x[wid * 32 + lane];
    int   c  = g_cnt[wid];
    float av = (c > 0) ? g_agg[wid * 32 + lane] / (float)c : 0.f;
    float acc = linb[j];
#pragma unroll
    for (int k = 0; k < 64; k++) {
        float src = (k < 32) ? xv : av;
        float b   = __shfl_sync(0xffffffffu, src, k & 31);
        acc = fmaf(b, sW[k * OUT + j], acc);
    }
    acc = (acc > 0.f) ? acc : 0.01f * acc;
    if (lane < OUT) xo[wid * OUT + lane] = acc;
}

// ---------------- scoring: dot(final[user_node], final[item]) --------------------
__global__ void __launch_bounds__(256) score_kernel(const int* __restrict__ users,
                                                    const int* __restrict__ items,
                                                    float* __restrict__ out) {
    int wid = (blockIdx.x * 256 + threadIdx.x) >> 5;
    if (wid >= BATCH) return;
    int lane = threadIdx.x & 31;
    int un = N_ENT + users[wid];
    int it = items[wid];
    float s = g_x1[(size_t)un * 32 + lane] * g_x1[(size_t)it * 32 + lane];
    if (lane < 16) s += g_x2[(size_t)un * 16 + lane] * g_x2[(size_t)it * 16 + lane];
#pragma unroll
    for (int o = 16; o; o >>= 1) s += __shfl_xor_sync(0xffffffffu, s, o);
    if (lane == 0) out[wid] = s;
}

__global__ void finalize_kernel(float* out, int out_size) {
    if (threadIdx.x == 0 && out_size > BATCH)
        out[BATCH] = g_loss * (1.0f / (float)(NND * 64));
}

// ---------------- host launcher --------------------------------------------------
extern "C" void kernel_launch(void* const* d_in, const int* in_sizes, int n_in,
                              void* d_out, int out_size) {
    int iu = 0, ii = 1, ies = 2, ied = 3, ier = 4, ient = 5, iusr = 6;
    int ie0 = 7, ib0 = 8, ie1 = 9, ib1 = 10, id0 = 11, idb0 = 12, id1 = 13, idb1 = 14;
    int iWr1 = 15, ilW1 = 16, ilb1 = 17, iWr2 = 18, ilW2 = 19, ilb2 = 20;
    bool dict_order = (n_in >= 21 && in_sizes[0] == BATCH && in_sizes[2] == NEDGE &&
                       in_sizes[5] == N_ENT * 64);
    if (!dict_order) {
        ient = 0; iusr = 1; ie0 = 2; ib0 = 3; ie1 = 4; ib1 = 5;
        id0 = 6; idb0 = 7; id1 = 8; idb1 = 9;
        iWr1 = 10; ilW1 = 11; ilb1 = 12; iWr2 = 13; ilW2 = 14; ilb2 = 15;
        iu = 16; ii = 17; ies = 18; ied = 19; ier = 20;
    }
    const int* users = (const int*)d_in[iu];
    const int* items = (const int*)d_in[ii];
    const int* esrc  = (const int*)d_in[ies];
    const int* edst  = (const int*)d_in[ied];
    const int* erel  = (const int*)d_in[ier];
    const float* ent = (const float*)d_in[ient];
    const float* usr = (const float*)d_in[iusr];
    float* out = (float*)d_out;

    static bool attr_done = false;
    if (!attr_done) {
        cudaFuncSetAttribute(encode_kernel, cudaFuncAttributeMaxDynamicSharedMemorySize, 65536);
        cudaFuncSetAttribute(decode_kernel, cudaFuncAttributeMaxDynamicSharedMemorySize, 65536);
        attr_done = true;
    }

    zero_all_kernel<<<1920, 256>>>();
    wsum_kernel<<<8, 256>>>((const float*)d_in[iWr1], (const float*)d_in[iWr2]);
    count_kernel<<<(NEDGE + 255) / 256, 256>>>(edst);
    encode_kernel<<<444, 256, 65536>>>(ent, usr,
                                (const float*)d_in[ie0], (const float*)d_in[ib0],
                                (const float*)d_in[ie1], (const float*)d_in[ib1]);
    decode_kernel<<<444, 256, 65536>>>(ent, usr,
                                (const float*)d_in[id0], (const float*)d_in[idb0],
                                (const float*)d_in[id1], (const float*)d_in[idb1]);
    // layer 1
    gate_kernel<<<(NND + 7) / 8, 256>>>(1);
    edge_kernel<<<NEDGE * 8 / 256, 256>>>(1, esrc, edst, erel);
    combine_kernel<1><<<(NND + 7) / 8, 256>>>((const float*)d_in[ilW1],
                                              (const float*)d_in[ilb1]);
    // layer 2
    zero_agg_kernel<<<1920, 256>>>();
    gate_kernel<<<(NND + 7) / 8, 256>>>(2);
    edge_kernel<<<NEDGE * 8 / 256, 256>>>(2, esrc, edst, erel);
    combine_kernel<2><<<(NND + 7) / 8, 256>>>((const float*)d_in[ilW2],
                                              (const float*)d_in[ilb2]);
    // outputs
    score_kernel<<<(BATCH * 32 + 255) / 256, 256>>>(users, items, out);
    finalize_kernel<<<1, 32>>>(out, out_size);
}